// round 12
// baseline (speedup 1.0000x reference)
#include <cuda_runtime.h>
#include <cuda_bf16.h>
#include <cstdint>

#define BATCH 16
#define CIN   1024
#define CPD   512
#define SS    1024   // H*W

// ---------------- scratch (device globals) ----------------
__device__ float  d_z[(size_t)BATCH * CIN * SS];
__device__ double d_red[BATCH][8];   // 0..2: Sg,Spg,Sp2g  3,4: sum z, sum z^2

__device__ __nv_bfloat16 d_Whi[(size_t)1536 * CIN];   // Wt|Wp|Wg stacked
__device__ __nv_bfloat16 d_Wlo[(size_t)1536 * CIN];
__device__ __nv_bfloat16 d_Wzhi[(size_t)CIN * CPD];
__device__ __nv_bfloat16 d_Wzlo[(size_t)CIN * CPD];
__device__ __nv_bfloat16 d_xThi[(size_t)BATCH * SS * CIN];  // x^T [b][s][c]
__device__ __nv_bfloat16 d_xTlo[(size_t)BATCH * SS * CIN];
__device__ __nv_bfloat16 d_tThi[(size_t)BATCH * SS * CPD];  // t^T [b][s][cp]
__device__ __nv_bfloat16 d_tTlo[(size_t)BATCH * SS * CPD];
__device__ __nv_bfloat16 d_yThi[(size_t)BATCH * SS * CPD];  // y^T [b][s][cp]
__device__ __nv_bfloat16 d_yTlo[(size_t)BATCH * SS * CPD];

// ---------------- helpers ----------------
__device__ __forceinline__ uint32_t smem_to_u32(const void* p) {
    uint32_t a;
    asm("{ .reg .u64 t; cvta.to.shared.u64 t, %1; cvt.u32.u64 %0, t; }" : "=r"(a) : "l"(p));
    return a;
}
__device__ __forceinline__ void cp16(uint32_t s, const void* g) {
    asm volatile("cp.async.cg.shared.global [%0], [%1], 16;" :: "r"(s), "l"(g));
}
#define CP_COMMIT() asm volatile("cp.async.commit_group;" ::: "memory")
#define CP_WAIT0()  asm volatile("cp.async.wait_group 0;"  ::: "memory")

__device__ __forceinline__ void ldsm4(uint32_t* r, uint32_t addr) {
    asm volatile("ldmatrix.sync.aligned.m8n8.x4.shared.b16 {%0,%1,%2,%3}, [%4];"
                 : "=r"(r[0]), "=r"(r[1]), "=r"(r[2]), "=r"(r[3]) : "r"(addr));
}
__device__ __forceinline__ void mma16816(float* c, const uint32_t* a, const uint32_t* b) {
    asm volatile(
        "mma.sync.aligned.m16n8k16.row.col.f32.bf16.bf16.f32 "
        "{%0,%1,%2,%3}, {%4,%5,%6,%7}, {%8,%9}, {%0,%1,%2,%3};"
        : "+f"(c[0]), "+f"(c[1]), "+f"(c[2]), "+f"(c[3])
        : "r"(a[0]), "r"(a[1]), "r"(a[2]), "r"(a[3]), "r"(b[0]), "r"(b[1]));
}

// ---------------- SMEM tile geometry ----------------
#define RS_B      144                    // 128x64 bf16 tile, 144B row stride
#define TILE_B    (128 * RS_B)           // 18432
#define STAGE4_B  (4 * TILE_B)           // 73728  (Ahi,Alo,Bhi,Blo)
#define STAGE6_B  (6 * TILE_B)           // 110592 (Aphi,Aplo,Aghi,Aglo,Bhi,Blo)
#define SMEM_PG   (2 * STAGE6_B)         // 221184
#define SMEM_TZ   (2 * STAGE4_B)         // 147456

// ---------------- frag macros ----------------
#define LOAD_A(AH, AL, OHI, OLO, KK)                                          \
    {                                                                         \
        const uint32_t col_ = (uint32_t)(KK) * 32;                            \
        _Pragma("unroll")                                                     \
        for (int mf_ = 0; mf_ < 4; mf_++) {                                   \
            ldsm4(AH[mf_], scur + (OHI) + aoff[mf_] + col_);                  \
            ldsm4(AL[mf_], scur + (OLO) + aoff[mf_] + col_);                  \
        }                                                                     \
    }
#define LOAD_B(BH, BL, OHI, OLO, KK)                                          \
    {                                                                         \
        const uint32_t col_ = (uint32_t)(KK) * 32;                            \
        _Pragma("unroll")                                                     \
        for (int nfp_ = 0; nfp_ < 2; nfp_++) {                                \
            uint32_t rb_[4];                                                  \
            ldsm4(rb_, scur + (OHI) + boff[nfp_] + col_);                     \
            BH[2*nfp_][0]=rb_[0]; BH[2*nfp_][1]=rb_[1];                       \
            BH[2*nfp_+1][0]=rb_[2]; BH[2*nfp_+1][1]=rb_[3];                   \
            ldsm4(rb_, scur + (OLO) + boff[nfp_] + col_);                     \
            BL[2*nfp_][0]=rb_[0]; BL[2*nfp_][1]=rb_[1];                       \
            BL[2*nfp_+1][0]=rb_[2]; BL[2*nfp_+1][1]=rb_[3];                   \
        }                                                                     \
    }
#define MMA_ALL(ACC, AH, AL, BH, BL)                                          \
    _Pragma("unroll")                                                         \
    for (int mf_ = 0; mf_ < 4; mf_++)                                         \
        _Pragma("unroll")                                                     \
        for (int nf_ = 0; nf_ < 4; nf_++) {                                   \
            mma16816(ACC[mf_][nf_], AH[mf_], BH[nf_]);                        \
            mma16816(ACC[mf_][nf_], AH[mf_], BL[nf_]);                        \
            mma16816(ACC[mf_][nf_], AL[mf_], BH[nf_]);                        \
        }

#define DECL_FRAG_IDX()                                                       \
    const int tid  = threadIdx.x;                                             \
    const int b    = blockIdx.z;                                              \
    const int warp = tid >> 5, lane = tid & 31;                               \
    const int wm = warp >> 2, wn = warp & 3;                                  \
    const int grp = lane >> 2, qid = lane & 3;                                \
    const int mrow = lane & 7, msel = lane >> 3;                              \
    uint32_t aoff[4], boff[2];                                                \
    _Pragma("unroll")                                                         \
    for (int mf = 0; mf < 4; mf++)                                            \
        aoff[mf] = (uint32_t)(wm * 64 + mf * 16 + (msel & 1) * 8 + mrow) * RS_B \
                 + (uint32_t)(msel >> 1) * 16;                                \
    _Pragma("unroll")                                                         \
    for (int nfp = 0; nfp < 2; nfp++)                                         \
        boff[nfp] = (uint32_t)(wn * 32 + (2 * nfp + (msel >> 1)) * 8 + mrow) * RS_B \
                  + (uint32_t)(msel & 1) * 16;                                \
    (void)grp; (void)qid;

// ---------------- misc small kernels ----------------
__global__ void zero_red_kernel() {
    int i = threadIdx.x;
    if (i < BATCH * 8) ((double*)d_red)[i] = 0.0;
}

__global__ void split_w_kernel(const float* __restrict__ Wt, const float* __restrict__ Wp,
                               const float* __restrict__ Wg, const float* __restrict__ Wz) {
    size_t i = (size_t)blockIdx.x * 256 + threadIdx.x;
    if (i < (size_t)1536 * CIN) {
        int r = (int)(i >> 10), c = (int)(i & 1023);
        const float* W = (r < 512) ? Wt : ((r < 1024) ? Wp : Wg);
        float v = W[(size_t)(r & 511) * CIN + c];
        __nv_bfloat16 h = __float2bfloat16(v);
        d_Whi[i] = h;
        d_Wlo[i] = __float2bfloat16(v - __bfloat162float(h));
    }
    if (i < (size_t)CIN * CPD) {
        float v = Wz[i];
        __nv_bfloat16 h = __float2bfloat16(v);
        d_Wzhi[i] = h;
        d_Wzlo[i] = __float2bfloat16(v - __bfloat162float(h));
    }
}

// transpose+split x: [b][c][s] fp32 -> [b][s][c] bf16 hi/lo
__global__ void split_x_kernel(const float* __restrict__ x) {
    __shared__ float tile[32][33];
    int b = blockIdx.z, s0 = blockIdx.x * 32, c0 = blockIdx.y * 32;
    int tx = threadIdx.x, ty = threadIdx.y;
    const float* xp = x + ((size_t)b * CIN + c0) * SS + s0;
    for (int i = ty; i < 32; i += 8)
        tile[i][tx] = xp[(size_t)i * SS + tx];
    __syncthreads();
    __nv_bfloat16* oh = d_xThi + ((size_t)b * SS + s0) * CIN + c0;
    __nv_bfloat16* ol = d_xTlo + ((size_t)b * SS + s0) * CIN + c0;
    for (int i = ty; i < 32; i += 8) {
        float v = tile[tx][i];
        __nv_bfloat16 h = __float2bfloat16(v);
        oh[(size_t)i * CIN + tx] = h;
        ol[(size_t)i * CIN + tx] = __float2bfloat16(v - __bfloat162float(h));
    }
}

// y = c0 + c1 t + c2 t^2, elementwise on t^T hi/lo (already [b][s][cp])
__global__ void build_y_kernel() {
    size_t i2 = (size_t)blockIdx.x * 256 + threadIdx.x;   // handles 2 bf16 elems
    const size_t per_b2 = (size_t)SS * CPD / 2;           // 262144
    if (i2 >= per_b2 * BATCH) return;
    int b = (int)(i2 / per_b2);
    const double BETA = 0.9998000199986667;  // exp(-2e-4)
    float cf0 = (float)(BETA * d_red[b][0]);
    float cf1 = (float)(2e-4 * BETA * d_red[b][1]);
    float cf2 = (float)(2e-8 * BETA * d_red[b][2]);

    uint32_t hv = ((const uint32_t*)d_tThi)[i2];
    uint32_t lv = ((const uint32_t*)d_tTlo)[i2];
    __nv_bfloat162 h2 = *(__nv_bfloat162*)&hv;
    __nv_bfloat162 l2 = *(__nv_bfloat162*)&lv;
    float t0 = __bfloat162float(h2.x) + __bfloat162float(l2.x);
    float t1 = __bfloat162float(h2.y) + __bfloat162float(l2.y);
    float y0 = cf0 + t0 * (cf1 + cf2 * t0);
    float y1 = cf0 + t1 * (cf1 + cf2 * t1);
    __nv_bfloat16 yh0 = __float2bfloat16(y0), yh1 = __float2bfloat16(y1);
    __nv_bfloat162 oh{yh0, yh1};
    __nv_bfloat162 olv{__float2bfloat16(y0 - __bfloat162float(yh0)),
                       __float2bfloat16(y1 - __bfloat162float(yh1))};
    ((uint32_t*)d_yThi)[i2] = *(uint32_t*)&oh;
    ((uint32_t*)d_yTlo)[i2] = *(uint32_t*)&olv;
}

// ---------------- GEMM 1a: t = Wt @ x  (3-term, write t^T bf16 hi/lo) ----------------
__global__ __launch_bounds__(256, 1) void gemm_t_kernel() {
    extern __shared__ char smem[];
    const uint32_t sb = smem_to_u32(smem);
    DECL_FRAG_IDX();

    const __nv_bfloat16* gA0 = d_Whi + (size_t)blockIdx.x * 128 * CIN;
    const __nv_bfloat16* gA1 = d_Wlo + (size_t)blockIdx.x * 128 * CIN;
    const __nv_bfloat16* gB0 = d_xThi + ((size_t)b * SS + (size_t)blockIdx.y * 128) * CIN;
    const __nv_bfloat16* gB1 = d_xTlo + ((size_t)b * SS + (size_t)blockIdx.y * 128) * CIN;

    float acc[4][4][4];
#pragma unroll
    for (int i = 0; i < 4; i++)
#pragma unroll
        for (int j = 0; j < 4; j++)
#pragma unroll
            for (int v = 0; v < 4; v++) acc[i][j][v] = 0.f;

    auto load_stage = [&](uint32_t s, int k0) {
#pragma unroll
        for (int i = 0; i < 4; i++) {
            int ch  = tid + i * 256;
            int row = ch >> 3, cc = ch & 7;
            uint32_t so = (uint32_t)(row * RS_B + cc * 16);
            size_t   go = (size_t)row * CIN + k0 + cc * 8;
            cp16(s + 0 * TILE_B + so, gA0 + go);
            cp16(s + 1 * TILE_B + so, gA1 + go);
            cp16(s + 2 * TILE_B + so, gB0 + go);
            cp16(s + 3 * TILE_B + so, gB1 + go);
        }
    };

    load_stage(sb, 0);
    CP_COMMIT();

#pragma unroll 1
    for (int k = 0; k < CIN / 64; k++) {
        CP_WAIT0();
        __syncthreads();
        if (k + 1 < CIN / 64) {
            load_stage(sb + (uint32_t)((k + 1) & 1) * STAGE4_B, (k + 1) * 64);
            CP_COMMIT();
        }
        const uint32_t scur = sb + (uint32_t)(k & 1) * STAGE4_B;

        uint32_t ah0[4][4], al0[4][4], bh0[4][2], bl0[4][2];
        uint32_t ah1[4][4], al1[4][4], bh1[4][2], bl1[4][2];
        LOAD_A(ah0, al0, 0, TILE_B, 0); LOAD_B(bh0, bl0, 2 * TILE_B, 3 * TILE_B, 0);
        LOAD_A(ah1, al1, 0, TILE_B, 1); LOAD_B(bh1, bl1, 2 * TILE_B, 3 * TILE_B, 1);
        MMA_ALL(acc, ah0, al0, bh0, bl0);
        LOAD_A(ah0, al0, 0, TILE_B, 2); LOAD_B(bh0, bl0, 2 * TILE_B, 3 * TILE_B, 2);
        MMA_ALL(acc, ah1, al1, bh1, bl1);
        LOAD_A(ah1, al1, 0, TILE_B, 3); LOAD_B(bh1, bl1, 2 * TILE_B, 3 * TILE_B, 3);
        MMA_ALL(acc, ah0, al0, bh0, bl0);
        MMA_ALL(acc, ah1, al1, bh1, bl1);
    }
    __syncthreads();

    // transpose via smem, write t^T hi/lo bf16 [b][s][cp]
    float* ts = (float*)smem;   // [128 cp][133 s]
#pragma unroll
    for (int mf = 0; mf < 4; mf++) {
        const int r0 = wm * 64 + mf * 16 + grp;
#pragma unroll
        for (int nf = 0; nf < 4; nf++) {
            const int cg = wn * 32 + nf * 8 + qid * 2;
            ts[(size_t)r0 * 133 + cg]           = acc[mf][nf][0];
            ts[(size_t)r0 * 133 + cg + 1]       = acc[mf][nf][1];
            ts[(size_t)(r0 + 8) * 133 + cg]     = acc[mf][nf][2];
            ts[(size_t)(r0 + 8) * 133 + cg + 1] = acc[mf][nf][3];
        }
    }
    __syncthreads();
    const int cp0 = blockIdx.x * 128;
    const int s0g = blockIdx.y * 128;
#pragma unroll 1
    for (int sr = 0; sr < 16; sr++) {
        const int s_l = warp * 16 + sr;
        __nv_bfloat16* oh = d_tThi + ((size_t)b * SS + s0g + s_l) * CPD + cp0;
        __nv_bfloat16* ol = d_tTlo + ((size_t)b * SS + s0g + s_l) * CPD + cp0;
#pragma unroll
        for (int j = 0; j < 4; j++) {
            const int cp_l = j * 32 + lane;
            float v = ts[(size_t)cp_l * 133 + s_l];
            __nv_bfloat16 h = __float2bfloat16(v);
            oh[cp_l] = h;
            ol[cp_l] = __float2bfloat16(v - __bfloat162float(h));
        }
    }
}

// ---------------- GEMM 1b: fused p,g (shared B; only sums survive) ----------------
__global__ __launch_bounds__(256, 1) void gemm_pg_kernel() {
    extern __shared__ char smem[];
    const uint32_t sb = smem_to_u32(smem);
    DECL_FRAG_IDX();

    const int mt = blockIdx.x;   // 0..3
    const __nv_bfloat16* gp0 = d_Whi + (size_t)(512 + mt * 128) * CIN;   // Wp hi
    const __nv_bfloat16* gp1 = d_Wlo + (size_t)(512 + mt * 128) * CIN;   // Wp lo
    const __nv_bfloat16* gp2 = d_Whi + (size_t)(1024 + mt * 128) * CIN;  // Wg hi
    const __nv_bfloat16* gp3 = d_Wlo + (size_t)(1024 + mt * 128) * CIN;  // Wg lo
    const __nv_bfloat16* gp4 = d_xThi + ((size_t)b * SS + (size_t)blockIdx.y * 128) * CIN;
    const __nv_bfloat16* gp5 = d_xTlo + ((size_t)b * SS + (size_t)blockIdx.y * 128) * CIN;

    float accP[4][4][4], accG[4][4][4];
#pragma unroll
    for (int i = 0; i < 4; i++)
#pragma unroll
        for (int j = 0; j < 4; j++)
#pragma unroll
            for (int v = 0; v < 4; v++) { accP[i][j][v] = 0.f; accG[i][j][v] = 0.f; }

    auto load_stage = [&](uint32_t s, int k0) {
#pragma unroll
        for (int i = 0; i < 4; i++) {
            int ch  = tid + i * 256;
            int row = ch >> 3, cc = ch & 7;
            uint32_t so = (uint32_t)(row * RS_B + cc * 16);
            size_t   go = (size_t)row * CIN + k0 + cc * 8;
            cp16(s + 0 * TILE_B + so, gp0 + go);
            cp16(s + 1 * TILE_B + so, gp1 + go);
            cp16(s + 2 * TILE_B + so, gp2 + go);
            cp16(s + 3 * TILE_B + so, gp3 + go);
            cp16(s + 4 * TILE_B + so, gp4 + go);
            cp16(s + 5 * TILE_B + so, gp5 + go);
        }
    };

    load_stage(sb, 0);
    CP_COMMIT();

#pragma unroll 1
    for (int k = 0; k < CIN / 64; k++) {
        CP_WAIT0();
        __syncthreads();
        if (k + 1 < CIN / 64) {
            load_stage(sb + (uint32_t)((k + 1) & 1) * STAGE6_B, (k + 1) * 64);
            CP_COMMIT();
        }
        const uint32_t scur = sb + (uint32_t)(k & 1) * STAGE6_B;

#pragma unroll
        for (int kk = 0; kk < 4; kk++) {
            uint32_t ah[4][4], al[4][4], bh[4][2], bl[4][2];
            LOAD_B(bh, bl, 4 * TILE_B, 5 * TILE_B, kk);
            LOAD_A(ah, al, 0, TILE_B, kk);               // Wp
            MMA_ALL(accP, ah, al, bh, bl);
            LOAD_A(ah, al, 2 * TILE_B, 3 * TILE_B, kk);  // Wg
            MMA_ALL(accG, ah, al, bh, bl);
        }
    }
    __syncthreads();

    float s0 = 0.f, s1 = 0.f, s2 = 0.f;
#pragma unroll
    for (int mf = 0; mf < 4; mf++)
#pragma unroll
        for (int nf = 0; nf < 4; nf++)
#pragma unroll
            for (int v = 0; v < 4; v++) {
                float pv = accP[mf][nf][v], gv = accG[mf][nf][v];
                s0 += gv; s1 += pv * gv; s2 += pv * pv * gv;
            }
    double* sh0 = (double*)smem;
    double* sh1 = sh0 + 256;
    double* sh2 = sh1 + 256;
    sh0[tid] = (double)s0; sh1[tid] = (double)s1; sh2[tid] = (double)s2;
    __syncthreads();
    for (int off = 128; off > 0; off >>= 1) {
        if (tid < off) {
            sh0[tid] += sh0[tid + off];
            sh1[tid] += sh1[tid + off];
            sh2[tid] += sh2[tid + off];
        }
        __syncthreads();
    }
    if (tid == 0) {
        atomicAdd(&d_red[b][0], sh0[0]);
        atomicAdd(&d_red[b][1], sh1[0]);
        atomicAdd(&d_red[b][2], sh2[0]);
    }
}

// ---------------- GEMM 2: z = Wz @ y  (3-term, write z fp32 + GN sums) ----------------
__global__ __launch_bounds__(256, 1) void gemm_z_kernel() {
    extern __shared__ char smem[];
    const uint32_t sb = smem_to_u32(smem);
    DECL_FRAG_IDX();

    const __nv_bfloat16* gA0 = d_Wzhi + (size_t)blockIdx.x * 128 * CPD;
    const __nv_bfloat16* gA1 = d_Wzlo + (size_t)blockIdx.x * 128 * CPD;
    const __nv_bfloat16* gB0 = d_yThi + ((size_t)b * SS + (size_t)blockIdx.y * 128) * CPD;
    const __nv_bfloat16* gB1 = d_yTlo + ((size_t)b * SS + (size_t)blockIdx.y * 128) * CPD;

    float acc[4][4][4];
#pragma unroll
    for (int i = 0; i < 4; i++)
#pragma unroll
        for (int j = 0; j < 4; j++)
#pragma unroll
            for (int v = 0; v < 4; v++) acc[i][j][v] = 0.f;

    auto load_stage = [&](uint32_t s, int k0) {
#pragma unroll
        for (int i = 0; i < 4; i++) {
            int ch  = tid + i * 256;
            int row = ch >> 3, cc = ch & 7;
            uint32_t so = (uint32_t)(row * RS_B + cc * 16);
            size_t   go = (size_t)row * CPD + k0 + cc * 8;
            cp16(s + 0 * TILE_B + so, gA0 + go);
            cp16(s + 1 * TILE_B + so, gA1 + go);
            cp16(s + 2 * TILE_B + so, gB0 + go);
            cp16(s + 3 * TILE_B + so, gB1 + go);
        }
    };

    load_stage(sb, 0);
    CP_COMMIT();

#pragma unroll 1
    for (int k = 0; k < CPD / 64; k++) {
        CP_WAIT0();
        __syncthreads();
        if (k + 1 < CPD / 64) {
            load_stage(sb + (uint32_t)((k + 1) & 1) * STAGE4_B, (k + 1) * 64);
            CP_COMMIT();
        }
        const uint32_t scur = sb + (uint32_t)(k & 1) * STAGE4_B;

        uint32_t ah0[4][4], al0[4][4], bh0[4][2], bl0[4][2];
        uint32_t ah1[4][4], al1[4][4], bh1[4][2], bl1[4][2];
        LOAD_A(ah0, al0, 0, TILE_B, 0); LOAD_B(bh0, bl0, 2 * TILE_B, 3 * TILE_B, 0);
        LOAD_A(ah1, al1, 0, TILE_B, 1); LOAD_B(bh1, bl1, 2 * TILE_B, 3 * TILE_B, 1);
        MMA_ALL(acc, ah0, al0, bh0, bl0);
        LOAD_A(ah0, al0, 0, TILE_B, 2); LOAD_B(bh0, bl0, 2 * TILE_B, 3 * TILE_B, 2);
        MMA_ALL(acc, ah1, al1, bh1, bl1);
        LOAD_A(ah1, al1, 0, TILE_B, 3); LOAD_B(bh1, bl1, 2 * TILE_B, 3 * TILE_B, 3);
        MMA_ALL(acc, ah0, al0, bh0, bl0);
        MMA_ALL(acc, ah1, al1, bh1, bl1);
    }
    __syncthreads();

    float* outp = d_z + ((size_t)b * CIN + (size_t)blockIdx.x * 128) * SS
                + blockIdx.y * 128;
    float zs = 0.f, zq = 0.f;
#pragma unroll
    for (int mf = 0; mf < 4; mf++) {
        const int r0 = wm * 64 + mf * 16 + grp;
#pragma unroll
        for (int nf = 0; nf < 4; nf++) {
            const int cg = wn * 32 + nf * 8 + qid * 2;
            float2 v0 = {acc[mf][nf][0], acc[mf][nf][1]};
            float2 v1 = {acc[mf][nf][2], acc[mf][nf][3]};
            *(float2*)(outp + (size_t)r0 * SS + cg)       = v0;
            *(float2*)(outp + (size_t)(r0 + 8) * SS + cg) = v1;
            zs += v0.x + v0.y + v1.x + v1.y;
            zq += v0.x * v0.x + v0.y * v0.y + v1.x * v1.x + v1.y * v1.y;
        }
    }
    double* shs = (double*)smem;
    double* shq = shs + 256;
    shs[tid] = (double)zs; shq[tid] = (double)zq;
    __syncthreads();
    for (int off = 128; off > 0; off >>= 1) {
        if (tid < off) { shs[tid] += shs[tid + off]; shq[tid] += shq[tid + off]; }
        __syncthreads();
    }
    if (tid == 0) {
        atomicAdd(&d_red[b][3], shs[0]);
        atomicAdd(&d_red[b][4], shq[0]);
    }
}

// ---------------- finalize: out = (z - mu)*rsigma*gn_w + gn_b + x ----------------
__global__ void finalize_kernel(const float* __restrict__ x,
                                const float* __restrict__ gnw,
                                const float* __restrict__ gnb,
                                float* __restrict__ out) {
    size_t idx4 = (size_t)blockIdx.x * blockDim.x + threadIdx.x;
    const size_t total4 = (size_t)BATCH * CIN * SS / 4;
    if (idx4 >= total4) return;
    size_t idx = idx4 * 4;
    int b = (int)(idx / ((size_t)CIN * SS));
    int c = (int)((idx / SS) % CIN);

    const double n = (double)CIN * SS;
    double mu  = d_red[b][3] / n;
    double var = d_red[b][4] / n - mu * mu;
    float rs  = rsqrtf((float)var + 1e-5f);
    float fmu = (float)mu;
    float w = gnw[c] * rs;
    float bias = gnb[c];

    float4 zv = *(const float4*)(d_z + idx);
    float4 xv = *(const float4*)(x + idx);
    float4 o;
    o.x = (zv.x - fmu) * w + bias + xv.x;
    o.y = (zv.y - fmu) * w + bias + xv.y;
    o.z = (zv.z - fmu) * w + bias + xv.z;
    o.w = (zv.w - fmu) * w + bias + xv.w;
    *(float4*)(out + idx) = o;
}

extern "C" void kernel_launch(void* const* d_in, const int* in_sizes, int n_in,
                              void* d_out, int out_size) {
    const float* x   = (const float*)d_in[0];
    const float* Wt  = (const float*)d_in[1];
    const float* Wp  = (const float*)d_in[2];
    const float* Wg  = (const float*)d_in[3];
    const float* Wz  = (const float*)d_in[4];
    const float* gnw = (const float*)d_in[5];
    const float* gnb = (const float*)d_in[6];
    float* out = (float*)d_out;

    cudaFuncSetAttribute(gemm_t_kernel,  cudaFuncAttributeMaxDynamicSharedMemorySize, SMEM_TZ);
    cudaFuncSetAttribute(gemm_pg_kernel, cudaFuncAttributeMaxDynamicSharedMemorySize, SMEM_PG);
    cudaFuncSetAttribute(gemm_z_kernel,  cudaFuncAttributeMaxDynamicSharedMemorySize, SMEM_TZ);

    zero_red_kernel<<<1, 128>>>();
    split_w_kernel<<<6144, 256>>>(Wt, Wp, Wg, Wz);
    split_x_kernel<<<dim3(32, 32, 16), dim3(32, 8)>>>(x);

    gemm_pg_kernel<<<dim3(4, 8, 16), 256, SMEM_PG>>>();   // Sg, Spg, Sp2g
    gemm_t_kernel<<<dim3(4, 8, 16), 256, SMEM_TZ>>>();    // t^T bf16 hi/lo

    build_y_kernel<<<16384, 256>>>();

    gemm_z_kernel<<<dim3(8, 8, 16), 256, SMEM_TZ>>>();    // z + GN sums

    finalize_kernel<<<16384, 256>>>(x, gnw, gnb, out);
}

// round 16
// speedup vs baseline: 1.2709x; 1.2709x over previous
#include <cuda_runtime.h>
#include <cuda_bf16.h>
#include <cstdint>

#define BATCH 16
#define CIN   1024
#define CPD   512
#define SS    1024   // H*W

// ---------------- scratch (device globals) ----------------
__device__ float  d_t[(size_t)BATCH * CPD * SS];
__device__ float  d_p[(size_t)BATCH * CPD * SS];
__device__ float  d_g[(size_t)BATCH * CPD * SS];
__device__ float  d_z[(size_t)BATCH * CIN * SS];
__device__ double d_red[BATCH][8];   // 0..2: Sg,Spg,Sp2g  3,4: sum z, sum z^2

__device__ __nv_bfloat16 d_Whi[(size_t)1536 * CIN];   // Wt|Wp|Wg stacked
__device__ __nv_bfloat16 d_Wlo[(size_t)1536 * CIN];
__device__ __nv_bfloat16 d_Wzhi[(size_t)CIN * CPD];
__device__ __nv_bfloat16 d_Wzlo[(size_t)CIN * CPD];
__device__ __nv_bfloat16 d_xThi[(size_t)BATCH * SS * CIN];  // x^T [b][s][c]
__device__ __nv_bfloat16 d_xTlo[(size_t)BATCH * SS * CIN];
__device__ __nv_bfloat16 d_yThi[(size_t)BATCH * SS * CPD];  // y^T [b][s][cp]
__device__ __nv_bfloat16 d_yTlo[(size_t)BATCH * SS * CPD];

// ---------------- helpers ----------------
__device__ __forceinline__ uint32_t smem_to_u32(const void* p) {
    uint32_t a;
    asm("{ .reg .u64 t; cvta.to.shared.u64 t, %1; cvt.u32.u64 %0, t; }" : "=r"(a) : "l"(p));
    return a;
}
__device__ __forceinline__ void cp16(uint32_t s, const void* g) {
    asm volatile("cp.async.cg.shared.global [%0], [%1], 16;" :: "r"(s), "l"(g));
}
#define CP_COMMIT() asm volatile("cp.async.commit_group;" ::: "memory")
#define CP_WAIT1()  asm volatile("cp.async.wait_group 1;"  ::: "memory")
#define CP_WAIT0()  asm volatile("cp.async.wait_group 0;"  ::: "memory")

__device__ __forceinline__ void ldsm4(uint32_t* r, uint32_t addr) {
    asm volatile("ldmatrix.sync.aligned.m8n8.x4.shared.b16 {%0,%1,%2,%3}, [%4];"
                 : "=r"(r[0]), "=r"(r[1]), "=r"(r[2]), "=r"(r[3]) : "r"(addr));
}
__device__ __forceinline__ void mma16816(float* c, const uint32_t* a, const uint32_t* b) {
    asm volatile(
        "mma.sync.aligned.m16n8k16.row.col.f32.bf16.bf16.f32 "
        "{%0,%1,%2,%3}, {%4,%5,%6,%7}, {%8,%9}, {%0,%1,%2,%3};"
        : "+f"(c[0]), "+f"(c[1]), "+f"(c[2]), "+f"(c[3])
        : "r"(a[0]), "r"(a[1]), "r"(a[2]), "r"(a[3]), "r"(b[0]), "r"(b[1]));
}

// ---------------- SMEM layout ----------------
#define RS_B      144                    // 128x64 bf16 tile, 144B row stride
#define TILE_B    (128 * RS_B)           // 18432
#define OFF_AHI   0
#define OFF_ALO   (TILE_B)
#define OFF_BHI   (2 * TILE_B)
#define OFF_BLO   (3 * TILE_B)
#define STAGE_B   (4 * TILE_B)           // 73728
#define NSTAGE    3
#define SMEM_TOTAL (NSTAGE * STAGE_B)    // 221184

// ---------------- misc small kernels ----------------
__global__ void split_w_kernel(const float* __restrict__ Wt, const float* __restrict__ Wp,
                               const float* __restrict__ Wg, const float* __restrict__ Wz) {
    size_t i = (size_t)blockIdx.x * 256 + threadIdx.x;
    if (blockIdx.x == 0 && threadIdx.x < BATCH * 8)
        ((double*)d_red)[threadIdx.x] = 0.0;      // zero reductions (consumed 2+ launches later)
    if (i < (size_t)1536 * CIN) {
        int r = (int)(i >> 10), c = (int)(i & 1023);
        const float* W = (r < 512) ? Wt : ((r < 1024) ? Wp : Wg);
        float v = W[(size_t)(r & 511) * CIN + c];
        __nv_bfloat16 h = __float2bfloat16(v);
        d_Whi[i] = h;
        d_Wlo[i] = __float2bfloat16(v - __bfloat162float(h));
    }
    if (i < (size_t)CIN * CPD) {
        float v = Wz[i];
        __nv_bfloat16 h = __float2bfloat16(v);
        d_Wzhi[i] = h;
        d_Wzlo[i] = __float2bfloat16(v - __bfloat162float(h));
    }
}

// transpose+split x: [b][c][s] fp32 -> [b][s][c] bf16 hi/lo
__global__ void split_x_kernel(const float* __restrict__ x) {
    __shared__ float tile[32][33];
    int b = blockIdx.z, s0 = blockIdx.x * 32, c0 = blockIdx.y * 32;
    int tx = threadIdx.x, ty = threadIdx.y;
    const float* xp = x + ((size_t)b * CIN + c0) * SS + s0;
    for (int i = ty; i < 32; i += 8)
        tile[i][tx] = xp[(size_t)i * SS + tx];
    __syncthreads();
    __nv_bfloat16* oh = d_xThi + ((size_t)b * SS + s0) * CIN + c0;
    __nv_bfloat16* ol = d_xTlo + ((size_t)b * SS + s0) * CIN + c0;
    for (int i = ty; i < 32; i += 8) {
        float v = tile[tx][i];
        __nv_bfloat16 h = __float2bfloat16(v);
        oh[(size_t)i * CIN + tx] = h;
        ol[(size_t)i * CIN + tx] = __float2bfloat16(v - __bfloat162float(h));
    }
}

// y = c0 + c1 t + c2 t^2, transposed+split: d_t [b][cp][s] -> [b][s][cp] bf16 hi/lo
__global__ void build_y_kernel() {
    __shared__ float tile[32][33];
    int b = blockIdx.z, s0 = blockIdx.x * 32, c0 = blockIdx.y * 32;
    int tx = threadIdx.x, ty = threadIdx.y;
    const double BETA = 0.9998000199986667;  // exp(-2e-4)
    float cf0 = (float)(BETA * d_red[b][0]);
    float cf1 = (float)(2e-4 * BETA * d_red[b][1]);
    float cf2 = (float)(2e-8 * BETA * d_red[b][2]);
    const float* tp = d_t + ((size_t)b * CPD + c0) * SS + s0;
    for (int i = ty; i < 32; i += 8)
        tile[i][tx] = tp[(size_t)i * SS + tx];
    __syncthreads();
    __nv_bfloat16* oh = d_yThi + ((size_t)b * SS + s0) * CPD + c0;
    __nv_bfloat16* ol = d_yTlo + ((size_t)b * SS + s0) * CPD + c0;
    for (int i = ty; i < 32; i += 8) {
        float t = tile[tx][i];
        float y = cf0 + t * (cf1 + cf2 * t);
        __nv_bfloat16 h = __float2bfloat16(y);
        oh[(size_t)i * CPD + tx] = h;
        ol[(size_t)i * CPD + tx] = __float2bfloat16(y - __bfloat162float(h));
    }
}

__global__ void reduce_pg_kernel() {
    const int b = blockIdx.y;
    const float* p = d_p + (size_t)b * CPD * SS;
    const float* g = d_g + (size_t)b * CPD * SS;
    const int n = CPD * SS;
    double s0 = 0, s1 = 0, s2 = 0;
    for (int i = blockIdx.x * blockDim.x + threadIdx.x; i < n; i += gridDim.x * blockDim.x) {
        float pv = p[i], gv = g[i];
        s0 += (double)gv;
        s1 += (double)pv * gv;
        s2 += (double)pv * pv * gv;
    }
    __shared__ double sh0[256], sh1[256], sh2[256];
    sh0[threadIdx.x] = s0; sh1[threadIdx.x] = s1; sh2[threadIdx.x] = s2;
    __syncthreads();
    for (int off = 128; off > 0; off >>= 1) {
        if (threadIdx.x < off) {
            sh0[threadIdx.x] += sh0[threadIdx.x + off];
            sh1[threadIdx.x] += sh1[threadIdx.x + off];
            sh2[threadIdx.x] += sh2[threadIdx.x + off];
        }
        __syncthreads();
    }
    if (threadIdx.x == 0) {
        atomicAdd(&d_red[b][0], sh0[0]);
        atomicAdd(&d_red[b][1], sh1[0]);
        atomicAdd(&d_red[b][2], sh2[0]);
    }
}

// ---------------- HMMA GEMM (WHICH=0: t/p/g, WHICH=1: z) ----------------
// C[128x128] per CTA. A [128][K] row-major (hi/lo), B [128][K] row-major.
// K-step 64, 3-stage cp.async pipeline, ldmatrix fragment loads.
// (r9 champion mainloop — unchanged)
template <int WHICH>
__global__ __launch_bounds__(256, 1) void gemm_hmma_kernel() {
    extern __shared__ char smem[];
    const uint32_t sb = smem_to_u32(smem);

    const int tid  = threadIdx.x;
    const int b    = blockIdx.z;
    const int warp = tid >> 5, lane = tid & 31;
    const int wm = warp >> 2, wn = warp & 3;       // 2 x 4 warp grid
    const int grp = lane >> 2, qid = lane & 3;
    const int mrow = lane & 7, msel = lane >> 3;   // ldmatrix lane mapping

    constexpr int NK  = (WHICH == 0) ? (CIN / 64) : (CPD / 64);
    constexpr int LDK = (WHICH == 0) ? CIN : CPD;

    const __nv_bfloat16 *gAhi, *gAlo, *gBhi, *gBlo;
    if (WHICH == 0) {
        gAhi = d_Whi + (size_t)blockIdx.x * 128 * CIN;
        gAlo = d_Wlo + (size_t)blockIdx.x * 128 * CIN;
        gBhi = d_xThi + ((size_t)b * SS + (size_t)blockIdx.y * 128) * CIN;
        gBlo = d_xTlo + ((size_t)b * SS + (size_t)blockIdx.y * 128) * CIN;
    } else {
        gAhi = d_Wzhi + (size_t)blockIdx.x * 128 * CPD;
        gAlo = d_Wzlo + (size_t)blockIdx.x * 128 * CPD;
        gBhi = d_yThi + ((size_t)b * SS + (size_t)blockIdx.y * 128) * CPD;
        gBlo = d_yTlo + ((size_t)b * SS + (size_t)blockIdx.y * 128) * CPD;
    }

    float acc[4][4][4];
#pragma unroll
    for (int i = 0; i < 4; i++)
#pragma unroll
        for (int j = 0; j < 4; j++)
#pragma unroll
            for (int v = 0; v < 4; v++) acc[i][j][v] = 0.f;

    // ldmatrix per-lane base offsets (without kk column advance)
    uint32_t aoff[4], boff[2];
#pragma unroll
    for (int mf = 0; mf < 4; mf++)
        aoff[mf] = (uint32_t)(wm * 64 + mf * 16 + (msel & 1) * 8 + mrow) * RS_B
                 + (uint32_t)(msel >> 1) * 16;
#pragma unroll
    for (int nfp = 0; nfp < 2; nfp++)
        boff[nfp] = (uint32_t)(wn * 32 + (2 * nfp + (msel >> 1)) * 8 + mrow) * RS_B
                  + (uint32_t)(msel & 1) * 16;

    // loader: 1024 16B-chunks per tensor (128 rows x 8 chunks), 4 per thread per tensor
    auto load_stage = [&](uint32_t s, int k0) {
#pragma unroll
        for (int i = 0; i < 4; i++) {
            int ch  = tid + i * 256;            // 0..1023
            int row = ch >> 3, cc = ch & 7;
            uint32_t so = (uint32_t)(row * RS_B + cc * 16);
            size_t   go = (size_t)row * LDK + k0 + cc * 8;
            cp16(s + OFF_AHI + so, gAhi + go);
            cp16(s + OFF_ALO + so, gAlo + go);
            cp16(s + OFF_BHI + so, gBhi + go);
            cp16(s + OFF_BLO + so, gBlo + go);
        }
    };

    load_stage(sb, 0);
    CP_COMMIT();
    load_stage(sb + STAGE_B, 64);
    CP_COMMIT();

    for (int k = 0; k < NK; k++) {
        if (k + 1 < NK) { CP_WAIT1(); } else { CP_WAIT0(); }
        __syncthreads();                         // stage k visible; all warps past k-1
        if (k + 2 < NK) {
            load_stage(sb + (uint32_t)((k + 2) % NSTAGE) * STAGE_B, (k + 2) * 64);
            CP_COMMIT();
        }
        const uint32_t scur = sb + (uint32_t)(k % NSTAGE) * STAGE_B;

#pragma unroll
        for (int kk = 0; kk < 4; kk++) {
            const uint32_t col = (uint32_t)kk * 32;
            uint32_t ah[4][4], al[4][4], bh[4][2], bl[4][2];
#pragma unroll
            for (int mf = 0; mf < 4; mf++) {
                ldsm4(ah[mf], scur + OFF_AHI + aoff[mf] + col);
                ldsm4(al[mf], scur + OFF_ALO + aoff[mf] + col);
            }
#pragma unroll
            for (int nfp = 0; nfp < 2; nfp++) {
                uint32_t rb[4];
                ldsm4(rb, scur + OFF_BHI + boff[nfp] + col);
                bh[2 * nfp][0] = rb[0]; bh[2 * nfp][1] = rb[1];
                bh[2 * nfp + 1][0] = rb[2]; bh[2 * nfp + 1][1] = rb[3];
                ldsm4(rb, scur + OFF_BLO + boff[nfp] + col);
                bl[2 * nfp][0] = rb[0]; bl[2 * nfp][1] = rb[1];
                bl[2 * nfp + 1][0] = rb[2]; bl[2 * nfp + 1][1] = rb[3];
            }
#pragma unroll
            for (int mf = 0; mf < 4; mf++)
#pragma unroll
                for (int nf = 0; nf < 4; nf++) {
                    mma16816(acc[mf][nf], ah[mf], bh[nf]);
                    mma16816(acc[mf][nf], ah[mf], bl[nf]);
                    mma16816(acc[mf][nf], al[mf], bh[nf]);
                }
        }
        // no trailing sync: next iteration's sync protects buffer reuse
    }

    // -------- epilogue: write C[128x128], rows=out-channel, cols=spatial --------
    float* outp;
    if (WHICH == 0) {
        const int mt = blockIdx.x, mat = mt >> 2;
        float* Cb = (mat == 0) ? d_t : ((mat == 1) ? d_p : d_g);
        outp = Cb + ((size_t)b * CPD + (size_t)(mt & 3) * 128) * SS + blockIdx.y * 128;
    } else {
        outp = d_z + ((size_t)b * CIN + (size_t)blockIdx.x * 128) * SS + blockIdx.y * 128;
    }

    double zs = 0.0, zq = 0.0;
#pragma unroll
    for (int mf = 0; mf < 4; mf++) {
        const int r0 = wm * 64 + mf * 16 + grp;
#pragma unroll
        for (int nf = 0; nf < 4; nf++) {
            const int cg = wn * 32 + nf * 8 + qid * 2;
            float2 v0 = {acc[mf][nf][0], acc[mf][nf][1]};
            float2 v1 = {acc[mf][nf][2], acc[mf][nf][3]};
            *(float2*)(outp + (size_t)r0 * SS + cg)       = v0;
            *(float2*)(outp + (size_t)(r0 + 8) * SS + cg) = v1;
            if (WHICH == 1) {
                zs += (double)v0.x + v0.y + (double)v1.x + v1.y;
                zq += (double)v0.x * v0.x + (double)v0.y * v0.y
                    + (double)v1.x * v1.x + (double)v1.y * v1.y;
            }
        }
    }

    if (WHICH == 1) {
        __syncthreads();                       // smem free for reduction
        double* shs = (double*)smem;
        double* shq = shs + 256;
        shs[tid] = zs; shq[tid] = zq;
        __syncthreads();
        for (int off = 128; off > 0; off >>= 1) {
            if (tid < off) { shs[tid] += shs[tid + off]; shq[tid] += shq[tid + off]; }
            __syncthreads();
        }
        if (tid == 0) {
            atomicAdd(&d_red[b][3], shs[0]);
            atomicAdd(&d_red[b][4], shq[0]);
        }
    }
}

// ---------------- finalize: out = (z - mu)*rsigma*gn_w + gn_b + x ----------------
__global__ void finalize_kernel(const float* __restrict__ x,
                                const float* __restrict__ gnw,
                                const float* __restrict__ gnb,
                                float* __restrict__ out) {
    size_t idx4 = (size_t)blockIdx.x * blockDim.x + threadIdx.x;
    const size_t total4 = (size_t)BATCH * CIN * SS / 4;
    if (idx4 >= total4) return;
    size_t idx = idx4 * 4;
    int b = (int)(idx / ((size_t)CIN * SS));
    int c = (int)((idx / SS) % CIN);

    const double n = (double)CIN * SS;
    double mu  = d_red[b][3] / n;
    double var = d_red[b][4] / n - mu * mu;
    float rs  = rsqrtf((float)var + 1e-5f);
    float fmu = (float)mu;
    float w = gnw[c] * rs;
    float bias = gnb[c];

    float4 zv = *(const float4*)(d_z + idx);
    float4 xv = *(const float4*)(x + idx);
    float4 o;
    o.x = (zv.x - fmu) * w + bias + xv.x;
    o.y = (zv.y - fmu) * w + bias + xv.y;
    o.z = (zv.z - fmu) * w + bias + xv.z;
    o.w = (zv.w - fmu) * w + bias + xv.w;
    *(float4*)(out + idx) = o;
}

extern "C" void kernel_launch(void* const* d_in, const int* in_sizes, int n_in,
                              void* d_out, int out_size) {
    const float* x   = (const float*)d_in[0];
    const float* Wt  = (const float*)d_in[1];
    const float* Wp  = (const float*)d_in[2];
    const float* Wg  = (const float*)d_in[3];
    const float* Wz  = (const float*)d_in[4];
    const float* gnw = (const float*)d_in[5];
    const float* gnb = (const float*)d_in[6];
    float* out = (float*)d_out;

    cudaFuncSetAttribute(gemm_hmma_kernel<0>, cudaFuncAttributeMaxDynamicSharedMemorySize, SMEM_TOTAL);
    cudaFuncSetAttribute(gemm_hmma_kernel<1>, cudaFuncAttributeMaxDynamicSharedMemorySize, SMEM_TOTAL);

    split_w_kernel<<<6144, 256>>>(Wt, Wp, Wg, Wz);   // also zeroes d_red
    split_x_kernel<<<dim3(32, 32, 16), dim3(32, 8)>>>(x);

    gemm_hmma_kernel<0><<<dim3(12, 8, 16), 256, SMEM_TOTAL>>>();   // t, p, g

    reduce_pg_kernel<<<dim3(64, 16), 256>>>();
    build_y_kernel<<<dim3(32, 16, 16), dim3(32, 8)>>>();

    gemm_hmma_kernel<1><<<dim3(8, 8, 16), 256, SMEM_TOTAL>>>();    // z + GN sums

    finalize_kernel<<<16384, 256>>>(x, gnw, gnb, out);
}

// round 17
// speedup vs baseline: 1.3976x; 1.0998x over previous
#include <cuda_runtime.h>
#include <cuda_bf16.h>
#include <cstdint>

#define BATCH 16
#define CIN   1024
#define CPD   512
#define SS    1024   // H*W

// ---------------- scratch (device globals) ----------------
__device__ float  d_t[(size_t)BATCH * CPD * SS];
__device__ float  d_p[(size_t)BATCH * CPD * SS];
__device__ float  d_g[(size_t)BATCH * CPD * SS];
__device__ float  d_z[(size_t)BATCH * CIN * SS];
__device__ double d_red[BATCH][8];   // 0..2: Sg,Spg,Sp2g  3,4: sum z, sum z^2

__device__ __nv_bfloat16 d_Whi[(size_t)1536 * CIN];   // Wt|Wp|Wg stacked
__device__ __nv_bfloat16 d_Wlo[(size_t)1536 * CIN];
__device__ __nv_bfloat16 d_Wzhi[(size_t)CIN * CPD];
__device__ __nv_bfloat16 d_Wzlo[(size_t)CIN * CPD];
__device__ __nv_bfloat16 d_xThi[(size_t)BATCH * SS * CIN];  // x^T [b][s][c]
__device__ __nv_bfloat16 d_xTlo[(size_t)BATCH * SS * CIN];
__device__ __nv_bfloat16 d_yThi[(size_t)BATCH * SS * CPD];  // y^T [b][s][cp]
__device__ __nv_bfloat16 d_yTlo[(size_t)BATCH * SS * CPD];

// ---------------- helpers ----------------
__device__ __forceinline__ uint32_t smem_to_u32(const void* p) {
    uint32_t a;
    asm("{ .reg .u64 t; cvta.to.shared.u64 t, %1; cvt.u32.u64 %0, t; }" : "=r"(a) : "l"(p));
    return a;
}
__device__ __forceinline__ void cp16(uint32_t s, const void* g) {
    asm volatile("cp.async.cg.shared.global [%0], [%1], 16;" :: "r"(s), "l"(g));
}
#define CP_COMMIT() asm volatile("cp.async.commit_group;" ::: "memory")
#define CP_WAIT1()  asm volatile("cp.async.wait_group 1;"  ::: "memory")
#define CP_WAIT0()  asm volatile("cp.async.wait_group 0;"  ::: "memory")

__device__ __forceinline__ void ldsm4(uint32_t* r, uint32_t addr) {
    asm volatile("ldmatrix.sync.aligned.m8n8.x4.shared.b16 {%0,%1,%2,%3}, [%4];"
                 : "=r"(r[0]), "=r"(r[1]), "=r"(r[2]), "=r"(r[3]) : "r"(addr));
}
__device__ __forceinline__ void mma16816(float* c, const uint32_t* a, const uint32_t* b) {
    asm volatile(
        "mma.sync.aligned.m16n8k16.row.col.f32.bf16.bf16.f32 "
        "{%0,%1,%2,%3}, {%4,%5,%6,%7}, {%8,%9}, {%0,%1,%2,%3};"
        : "+f"(c[0]), "+f"(c[1]), "+f"(c[2]), "+f"(c[3])
        : "r"(a[0]), "r"(a[1]), "r"(a[2]), "r"(a[3]), "r"(b[0]), "r"(b[1]));
}

// ---------------- SMEM layout ----------------
#define RS_B      144                    // 128x64 bf16 tile, 144B row stride
#define TILE_B    (128 * RS_B)           // 18432
#define OFF_AHI   0
#define OFF_ALO   (TILE_B)
#define OFF_BHI   (2 * TILE_B)
#define OFF_BLO   (3 * TILE_B)
#define STAGE_B   (4 * TILE_B)           // 73728
#define NSTAGE    3
#define SMEM_TOTAL (NSTAGE * STAGE_B)    // 221184

// ---------------- misc small kernels ----------------
__global__ void split_w_kernel(const float* __restrict__ Wt, const float* __restrict__ Wp,
                               const float* __restrict__ Wg, const float* __restrict__ Wz) {
    size_t i = (size_t)blockIdx.x * 256 + threadIdx.x;
    if (blockIdx.x == 0 && threadIdx.x < BATCH * 8)
        ((double*)d_red)[threadIdx.x] = 0.0;      // zero reductions (consumed 2+ launches later)
    if (i < (size_t)1536 * CIN) {
        int r = (int)(i >> 10), c = (int)(i & 1023);
        const float* W = (r < 512) ? Wt : ((r < 1024) ? Wp : Wg);
        float v = W[(size_t)(r & 511) * CIN + c];
        __nv_bfloat16 h = __float2bfloat16(v);
        d_Whi[i] = h;
        d_Wlo[i] = __float2bfloat16(v - __bfloat162float(h));
    }
    if (i < (size_t)CIN * CPD) {
        float v = Wz[i];
        __nv_bfloat16 h = __float2bfloat16(v);
        d_Wzhi[i] = h;
        d_Wzlo[i] = __float2bfloat16(v - __bfloat162float(h));
    }
}

// transpose+split x: [b][c][s] fp32 -> [b][s][c] bf16 hi/lo
__global__ void split_x_kernel(const float* __restrict__ x) {
    __shared__ float tile[32][33];
    int b = blockIdx.z, s0 = blockIdx.x * 32, c0 = blockIdx.y * 32;
    int tx = threadIdx.x, ty = threadIdx.y;
    const float* xp = x + ((size_t)b * CIN + c0) * SS + s0;
    for (int i = ty; i < 32; i += 8)
        tile[i][tx] = xp[(size_t)i * SS + tx];
    __syncthreads();
    __nv_bfloat16* oh = d_xThi + ((size_t)b * SS + s0) * CIN + c0;
    __nv_bfloat16* ol = d_xTlo + ((size_t)b * SS + s0) * CIN + c0;
    for (int i = ty; i < 32; i += 8) {
        float v = tile[tx][i];
        __nv_bfloat16 h = __float2bfloat16(v);
        oh[(size_t)i * CIN + tx] = h;
        ol[(size_t)i * CIN + tx] = __float2bfloat16(v - __bfloat162float(h));
    }
}

// y = c0 + c1 t + c2 t^2, transposed+split: d_t [b][cp][s] -> [b][s][cp] bf16 hi/lo
__global__ void build_y_kernel() {
    __shared__ float tile[32][33];
    int b = blockIdx.z, s0 = blockIdx.x * 32, c0 = blockIdx.y * 32;
    int tx = threadIdx.x, ty = threadIdx.y;
    const double BETA = 0.9998000199986667;  // exp(-2e-4)
    float cf0 = (float)(BETA * d_red[b][0]);
    float cf1 = (float)(2e-4 * BETA * d_red[b][1]);
    float cf2 = (float)(2e-8 * BETA * d_red[b][2]);
    const float* tp = d_t + ((size_t)b * CPD + c0) * SS + s0;
    for (int i = ty; i < 32; i += 8)
        tile[i][tx] = tp[(size_t)i * SS + tx];
    __syncthreads();
    __nv_bfloat16* oh = d_yThi + ((size_t)b * SS + s0) * CPD + c0;
    __nv_bfloat16* ol = d_yTlo + ((size_t)b * SS + s0) * CPD + c0;
    for (int i = ty; i < 32; i += 8) {
        float t = tile[tx][i];
        float y = cf0 + t * (cf1 + cf2 * t);
        __nv_bfloat16 h = __float2bfloat16(y);
        oh[(size_t)i * CPD + tx] = h;
        ol[(size_t)i * CPD + tx] = __float2bfloat16(y - __bfloat162float(h));
    }
}

// Sg, Spg, Sp2g per batch — fp32 multi-lane accumulators, float4 loads,
// double only at the block-combine (was: serial dependent DFMA chain, 107us).
__global__ void reduce_pg_kernel() {
    const int b = blockIdx.y;
    const float4* p4 = (const float4*)(d_p + (size_t)b * CPD * SS);
    const float4* g4 = (const float4*)(d_g + (size_t)b * CPD * SS);
    const int n4 = CPD * SS / 4;                 // 131072 float4 per batch

    float a0[4] = {0.f, 0.f, 0.f, 0.f};
    float a1[4] = {0.f, 0.f, 0.f, 0.f};
    float a2[4] = {0.f, 0.f, 0.f, 0.f};
    for (int i = blockIdx.x * blockDim.x + threadIdx.x; i < n4; i += gridDim.x * blockDim.x) {
        float4 pv = p4[i];
        float4 gv = g4[i];
        a0[0] += gv.x;            a0[1] += gv.y;
        a0[2] += gv.z;            a0[3] += gv.w;
        a1[0] += pv.x * gv.x;     a1[1] += pv.y * gv.y;
        a1[2] += pv.z * gv.z;     a1[3] += pv.w * gv.w;
        a2[0] += pv.x * pv.x * gv.x;  a2[1] += pv.y * pv.y * gv.y;
        a2[2] += pv.z * pv.z * gv.z;  a2[3] += pv.w * pv.w * gv.w;
    }
    double s0 = (double)a0[0] + a0[1] + a0[2] + a0[3];
    double s1 = (double)a1[0] + a1[1] + a1[2] + a1[3];
    double s2 = (double)a2[0] + a2[1] + a2[2] + a2[3];

    __shared__ double sh0[256], sh1[256], sh2[256];
    sh0[threadIdx.x] = s0; sh1[threadIdx.x] = s1; sh2[threadIdx.x] = s2;
    __syncthreads();
    for (int off = 128; off > 0; off >>= 1) {
        if (threadIdx.x < off) {
            sh0[threadIdx.x] += sh0[threadIdx.x + off];
            sh1[threadIdx.x] += sh1[threadIdx.x + off];
            sh2[threadIdx.x] += sh2[threadIdx.x + off];
        }
        __syncthreads();
    }
    if (threadIdx.x == 0) {
        atomicAdd(&d_red[b][0], sh0[0]);
        atomicAdd(&d_red[b][1], sh1[0]);
        atomicAdd(&d_red[b][2], sh2[0]);
    }
}

// ---------------- HMMA GEMM (WHICH=0: t/p/g, WHICH=1: z) ----------------
// C[128x128] per CTA. A [128][K] row-major (hi/lo), B [128][K] row-major.
// K-step 64, 3-stage cp.async pipeline, ldmatrix fragment loads.
// (r9/r16 champion mainloop — unchanged)
template <int WHICH>
__global__ __launch_bounds__(256, 1) void gemm_hmma_kernel() {
    extern __shared__ char smem[];
    const uint32_t sb = smem_to_u32(smem);

    const int tid  = threadIdx.x;
    const int b    = blockIdx.z;
    const int warp = tid >> 5, lane = tid & 31;
    const int wm = warp >> 2, wn = warp & 3;       // 2 x 4 warp grid
    const int grp = lane >> 2, qid = lane & 3;
    const int mrow = lane & 7, msel = lane >> 3;   // ldmatrix lane mapping

    constexpr int NK  = (WHICH == 0) ? (CIN / 64) : (CPD / 64);
    constexpr int LDK = (WHICH == 0) ? CIN : CPD;

    const __nv_bfloat16 *gAhi, *gAlo, *gBhi, *gBlo;
    if (WHICH == 0) {
        gAhi = d_Whi + (size_t)blockIdx.x * 128 * CIN;
        gAlo = d_Wlo + (size_t)blockIdx.x * 128 * CIN;
        gBhi = d_xThi + ((size_t)b * SS + (size_t)blockIdx.y * 128) * CIN;
        gBlo = d_xTlo + ((size_t)b * SS + (size_t)blockIdx.y * 128) * CIN;
    } else {
        gAhi = d_Wzhi + (size_t)blockIdx.x * 128 * CPD;
        gAlo = d_Wzlo + (size_t)blockIdx.x * 128 * CPD;
        gBhi = d_yThi + ((size_t)b * SS + (size_t)blockIdx.y * 128) * CPD;
        gBlo = d_yTlo + ((size_t)b * SS + (size_t)blockIdx.y * 128) * CPD;
    }

    float acc[4][4][4];
#pragma unroll
    for (int i = 0; i < 4; i++)
#pragma unroll
        for (int j = 0; j < 4; j++)
#pragma unroll
            for (int v = 0; v < 4; v++) acc[i][j][v] = 0.f;

    // ldmatrix per-lane base offsets (without kk column advance)
    uint32_t aoff[4], boff[2];
#pragma unroll
    for (int mf = 0; mf < 4; mf++)
        aoff[mf] = (uint32_t)(wm * 64 + mf * 16 + (msel & 1) * 8 + mrow) * RS_B
                 + (uint32_t)(msel >> 1) * 16;
#pragma unroll
    for (int nfp = 0; nfp < 2; nfp++)
        boff[nfp] = (uint32_t)(wn * 32 + (2 * nfp + (msel >> 1)) * 8 + mrow) * RS_B
                  + (uint32_t)(msel & 1) * 16;

    // loader: 1024 16B-chunks per tensor (128 rows x 8 chunks), 4 per thread per tensor
    auto load_stage = [&](uint32_t s, int k0) {
#pragma unroll
        for (int i = 0; i < 4; i++) {
            int ch  = tid + i * 256;            // 0..1023
            int row = ch >> 3, cc = ch & 7;
            uint32_t so = (uint32_t)(row * RS_B + cc * 16);
            size_t   go = (size_t)row * LDK + k0 + cc * 8;
            cp16(s + OFF_AHI + so, gAhi + go);
            cp16(s + OFF_ALO + so, gAlo + go);
            cp16(s + OFF_BHI + so, gBhi + go);
            cp16(s + OFF_BLO + so, gBlo + go);
        }
    };

    load_stage(sb, 0);
    CP_COMMIT();
    load_stage(sb + STAGE_B, 64);
    CP_COMMIT();

    for (int k = 0; k < NK; k++) {
        if (k + 1 < NK) { CP_WAIT1(); } else { CP_WAIT0(); }
        __syncthreads();                         // stage k visible; all warps past k-1
        if (k + 2 < NK) {
            load_stage(sb + (uint32_t)((k + 2) % NSTAGE) * STAGE_B, (k + 2) * 64);
            CP_COMMIT();
        }
        const uint32_t scur = sb + (uint32_t)(k % NSTAGE) * STAGE_B;

#pragma unroll
        for (int kk = 0; kk < 4; kk++) {
            const uint32_t col = (uint32_t)kk * 32;
            uint32_t ah[4][4], al[4][4], bh[4][2], bl[4][2];
#pragma unroll
            for (int mf = 0; mf < 4; mf++) {
                ldsm4(ah[mf], scur + OFF_AHI + aoff[mf] + col);
                ldsm4(al[mf], scur + OFF_ALO + aoff[mf] + col);
            }
#pragma unroll
            for (int nfp = 0; nfp < 2; nfp++) {
                uint32_t rb[4];
                ldsm4(rb, scur + OFF_BHI + boff[nfp] + col);
                bh[2 * nfp][0] = rb[0]; bh[2 * nfp][1] = rb[1];
                bh[2 * nfp + 1][0] = rb[2]; bh[2 * nfp + 1][1] = rb[3];
                ldsm4(rb, scur + OFF_BLO + boff[nfp] + col);
                bl[2 * nfp][0] = rb[0]; bl[2 * nfp][1] = rb[1];
                bl[2 * nfp + 1][0] = rb[2]; bl[2 * nfp + 1][1] = rb[3];
            }
#pragma unroll
            for (int mf = 0; mf < 4; mf++)
#pragma unroll
                for (int nf = 0; nf < 4; nf++) {
                    mma16816(acc[mf][nf], ah[mf], bh[nf]);
                    mma16816(acc[mf][nf], ah[mf], bl[nf]);
                    mma16816(acc[mf][nf], al[mf], bh[nf]);
                }
        }
        // no trailing sync: next iteration's sync protects buffer reuse
    }

    // -------- epilogue: write C[128x128], rows=out-channel, cols=spatial --------
    float* outp;
    if (WHICH == 0) {
        const int mt = blockIdx.x, mat = mt >> 2;
        float* Cb = (mat == 0) ? d_t : ((mat == 1) ? d_p : d_g);
        outp = Cb + ((size_t)b * CPD + (size_t)(mt & 3) * 128) * SS + blockIdx.y * 128;
    } else {
        outp = d_z + ((size_t)b * CIN + (size_t)blockIdx.x * 128) * SS + blockIdx.y * 128;
    }

    double zs = 0.0, zq = 0.0;
#pragma unroll
    for (int mf = 0; mf < 4; mf++) {
        const int r0 = wm * 64 + mf * 16 + grp;
#pragma unroll
        for (int nf = 0; nf < 4; nf++) {
            const int cg = wn * 32 + nf * 8 + qid * 2;
            float2 v0 = {acc[mf][nf][0], acc[mf][nf][1]};
            float2 v1 = {acc[mf][nf][2], acc[mf][nf][3]};
            *(float2*)(outp + (size_t)r0 * SS + cg)       = v0;
            *(float2*)(outp + (size_t)(r0 + 8) * SS + cg) = v1;
            if (WHICH == 1) {
                zs += (double)v0.x + v0.y + (double)v1.x + v1.y;
                zq += (double)v0.x * v0.x + (double)v0.y * v0.y
                    + (double)v1.x * v1.x + (double)v1.y * v1.y;
            }
        }
    }

    if (WHICH == 1) {
        __syncthreads();                       // smem free for reduction
        double* shs = (double*)smem;
        double* shq = shs + 256;
        shs[tid] = zs; shq[tid] = zq;
        __syncthreads();
        for (int off = 128; off > 0; off >>= 1) {
            if (tid < off) { shs[tid] += shs[tid + off]; shq[tid] += shq[tid + off]; }
            __syncthreads();
        }
        if (tid == 0) {
            atomicAdd(&d_red[b][3], shs[0]);
            atomicAdd(&d_red[b][4], shq[0]);
        }
    }
}

// ---------------- finalize: out = (z - mu)*rsigma*gn_w + gn_b + x ----------------
__global__ void finalize_kernel(const float* __restrict__ x,
                                const float* __restrict__ gnw,
                                const float* __restrict__ gnb,
                                float* __restrict__ out) {
    size_t idx4 = (size_t)blockIdx.x * blockDim.x + threadIdx.x;
    const size_t total4 = (size_t)BATCH * CIN * SS / 4;
    if (idx4 >= total4) return;
    size_t idx = idx4 * 4;
    int b = (int)(idx / ((size_t)CIN * SS));
    int c = (int)((idx / SS) % CIN);

    const double n = (double)CIN * SS;
    double mu  = d_red[b][3] / n;
    double var = d_red[b][4] / n - mu * mu;
    float rs  = rsqrtf((float)var + 1e-5f);
    float fmu = (float)mu;
    float w = gnw[c] * rs;
    float bias = gnb[c];

    float4 zv = *(const float4*)(d_z + idx);
    float4 xv = *(const float4*)(x + idx);
    float4 o;
    o.x = (zv.x - fmu) * w + bias + xv.x;
    o.y = (zv.y - fmu) * w + bias + xv.y;
    o.z = (zv.z - fmu) * w + bias + xv.z;
    o.w = (zv.w - fmu) * w + bias + xv.w;
    *(float4*)(out + idx) = o;
}

extern "C" void kernel_launch(void* const* d_in, const int* in_sizes, int n_in,
                              void* d_out, int out_size) {
    const float* x   = (const float*)d_in[0];
    const float* Wt  = (const float*)d_in[1];
    const float* Wp  = (const float*)d_in[2];
    const float* Wg  = (const float*)d_in[3];
    const float* Wz  = (const float*)d_in[4];
    const float* gnw = (const float*)d_in[5];
    const float* gnb = (const float*)d_in[6];
    float* out = (float*)d_out;

    cudaFuncSetAttribute(gemm_hmma_kernel<0>, cudaFuncAttributeMaxDynamicSharedMemorySize, SMEM_TOTAL);
    cudaFuncSetAttribute(gemm_hmma_kernel<1>, cudaFuncAttributeMaxDynamicSharedMemorySize, SMEM_TOTAL);

    split_w_kernel<<<6144, 256>>>(Wt, Wp, Wg, Wz);   // also zeroes d_red
    split_x_kernel<<<dim3(32, 32, 16), dim3(32, 8)>>>(x);

    gemm_hmma_kernel<0><<<dim3(12, 8, 16), 256, SMEM_TOTAL>>>();   // t, p, g

    reduce_pg_kernel<<<dim3(64, 16), 256>>>();
    build_y_kernel<<<dim3(32, 16, 16), dim3(32, 8)>>>();

    gemm_hmma_kernel<1><<<dim3(8, 8, 16), 256, SMEM_TOTAL>>>();    // z + GN sums

    finalize_kernel<<<16384, 256>>>(x, gnw, gnb, out);
}